// round 9
// baseline (speedup 1.0000x reference)
#include <cuda_runtime.h>
#include <cuda_fp16.h>
#include <cstdint>

// ============================================================================
// RPNHead via Winograd F(2x2,3x3). R9: GEMM re-tiled to CTA 128x128 with
// 256 threads and __launch_bounds__(256,2) so TWO independent CTAs co-reside
// per SM (register file was the occupancy wall at 512thr). Grid ordered so
// the 8 CTAs of one m-block are co-resident (A L1/L2-hot, U fully L2-res).
// ============================================================================
#define NPOS 131072
#define NTIL 32768
#define OFF_PROBS  3932160
#define OFF_DELTAS 7864320

__device__ __align__(1024) __half g_V [(size_t)16*NTIL*256];   // input transform
__device__ __align__(1024) __half g_wU[(size_t)16*512*256];    // weight transform
__device__ __align__(1024) __half g_M [(size_t)16*NTIL*512];   // GEMM results (fp16)
__device__ __align__(1024) __half g_sh[(size_t)NPOS*512];      // shared acts fp16
__device__ __align__(1024) __half g_wh[(size_t)128*512];       // head W [j][c]

__device__ __forceinline__ uint32_t smem_u32(const void* p) {
    uint32_t a;
    asm("{ .reg .u64 t; cvta.to.shared.u64 t, %1; cvt.u32.u64 %0, t; }"
        : "=r"(a) : "l"(p));
    return a;
}

#define CP_ASYNC16(dst, src, sz) \
    asm volatile("cp.async.cg.shared.global [%0], [%1], 16, %2;" \
        :: "r"((uint32_t)(dst)), "l"(src), "r"((int)(sz)) : "memory")
#define CP_COMMIT() asm volatile("cp.async.commit_group;" ::: "memory")
#define CP_WAIT1()  asm volatile("cp.async.wait_group 1;" ::: "memory")
#define CP_WAIT0()  asm volatile("cp.async.wait_group 0;" ::: "memory")

__device__ __forceinline__ void ldm4(uint32_t* f, uint32_t addr) {
    asm volatile("ldmatrix.sync.aligned.m8n8.x4.shared.b16 {%0,%1,%2,%3}, [%4];"
        : "=r"(f[0]), "=r"(f[1]), "=r"(f[2]), "=r"(f[3]) : "r"(addr));
}
__device__ __forceinline__ void mma16816(float* c, const uint32_t* a,
                                         uint32_t b0, uint32_t b1) {
    asm volatile("mma.sync.aligned.m16n8k16.row.col.f32.f16.f16.f32 "
        "{%0,%1,%2,%3}, {%4,%5,%6,%7}, {%8,%9}, {%0,%1,%2,%3};"
        : "+f"(c[0]), "+f"(c[1]), "+f"(c[2]), "+f"(c[3])
        : "r"(a[0]), "r"(a[1]), "r"(a[2]), "r"(a[3]), "r"(b0), "r"(b1));
}

// ============================================================================
// Kernel 1: input transform V = Bt d B (fp32 x -> fp16 V).
// ============================================================================
__global__ void wino_in_kernel(const float* __restrict__ x) {
    const int t = blockIdx.x;
    const int c2 = threadIdx.x;                 // channel pair
    const int tw = t & 63, th = (t >> 6) & 63, b = t >> 12;
    const int h0 = th * 2 - 1, w0 = tw * 2 - 1;

    float2 d[4][4];
    #pragma unroll
    for (int i = 0; i < 4; ++i) {
        const int h = h0 + i;
        const bool hv = (h >= 0) && (h < 128);
        #pragma unroll
        for (int j = 0; j < 4; ++j) {
            const int w_ = w0 + j;
            if (hv && w_ >= 0 && w_ < 128)
                d[i][j] = *reinterpret_cast<const float2*>(
                    x + ((size_t)((b * 128 + h) * 128 + w_)) * 256 + 2 * c2);
            else
                d[i][j] = make_float2(0.0f, 0.0f);
        }
    }
    float2 tr[4][4];
    #pragma unroll
    for (int j = 0; j < 4; ++j) {
        tr[0][j] = make_float2(d[0][j].x - d[2][j].x, d[0][j].y - d[2][j].y);
        tr[1][j] = make_float2(d[1][j].x + d[2][j].x, d[1][j].y + d[2][j].y);
        tr[2][j] = make_float2(d[2][j].x - d[1][j].x, d[2][j].y - d[1][j].y);
        tr[3][j] = make_float2(d[1][j].x - d[3][j].x, d[1][j].y - d[3][j].y);
    }
    #pragma unroll
    for (int i = 0; i < 4; ++i) {
        float2 v0 = make_float2(tr[i][0].x - tr[i][2].x, tr[i][0].y - tr[i][2].y);
        float2 v1 = make_float2(tr[i][1].x + tr[i][2].x, tr[i][1].y + tr[i][2].y);
        float2 v2 = make_float2(tr[i][2].x - tr[i][1].x, tr[i][2].y - tr[i][1].y);
        float2 v3 = make_float2(tr[i][1].x - tr[i][3].x, tr[i][1].y - tr[i][3].y);
        *reinterpret_cast<__half2*>(g_V + ((size_t)(i*4+0)*NTIL + t)*256 + 2*c2) = __floats2half2_rn(v0.x, v0.y);
        *reinterpret_cast<__half2*>(g_V + ((size_t)(i*4+1)*NTIL + t)*256 + 2*c2) = __floats2half2_rn(v1.x, v1.y);
        *reinterpret_cast<__half2*>(g_V + ((size_t)(i*4+2)*NTIL + t)*256 + 2*c2) = __floats2half2_rn(v2.x, v2.y);
        *reinterpret_cast<__half2*>(g_V + ((size_t)(i*4+3)*NTIL + t)*256 + 2*c2) = __floats2half2_rn(v3.x, v3.y);
    }
}

// ============================================================================
// Kernel 2: weight transform U = G g Gt. grid=512 (n), block=256 (c).
// ============================================================================
__global__ void wino_w_kernel(const float* __restrict__ ws) {
    const int n = blockIdx.x;
    const int c = threadIdx.x;
    float g[3][3];
    #pragma unroll
    for (int kh = 0; kh < 3; ++kh)
        #pragma unroll
        for (int kw = 0; kw < 3; ++kw)
            g[kh][kw] = ws[((size_t)(kh * 3 + kw) * 256 + c) * 512 + n];
    float u[4][3];
    #pragma unroll
    for (int kw = 0; kw < 3; ++kw) {
        u[0][kw] = g[0][kw];
        u[1][kw] = 0.5f * (g[0][kw] + g[1][kw] + g[2][kw]);
        u[2][kw] = 0.5f * (g[0][kw] - g[1][kw] + g[2][kw]);
        u[3][kw] = g[2][kw];
    }
    #pragma unroll
    for (int r = 0; r < 4; ++r) {
        float U0 = u[r][0];
        float U1 = 0.5f * (u[r][0] + u[r][1] + u[r][2]);
        float U2 = 0.5f * (u[r][0] - u[r][1] + u[r][2]);
        float U3 = u[r][2];
        g_wU[((size_t)(r * 4 + 0) * 512 + n) * 256 + c] = __float2half(U0);
        g_wU[((size_t)(r * 4 + 1) * 512 + n) * 256 + c] = __float2half(U1);
        g_wU[((size_t)(r * 4 + 2) * 512 + n) * 256 + c] = __float2half(U2);
        g_wU[((size_t)(r * 4 + 3) * 512 + n) * 256 + c] = __float2half(U3);
    }
}

// ============================================================================
// Kernel 3: head weight pack.
// ============================================================================
__global__ void cvt_wh_kernel(const float* __restrict__ wc, const float* __restrict__ wr) {
    const int j = blockIdx.x;    // 0..127
    const int c = threadIdx.x;   // 0..511
    float v = 0.0f;
    if (j < 30)      v = wc[c * 30 + j];
    else if (j < 90) v = wr[c * 60 + (j - 30)];
    g_wh[(size_t)j * 512 + c] = __float2half(v);
}

// ============================================================================
// Kernel 4: persistent batched GEMM, CTA tile 128x128, 256 thr, 2 CTAs/SM.
// grid = 2048: blockIdx = mblk*8 + nq*2 + chalf  (nq/chalf fastest so the
// 8 CTAs of one mblk co-reside: shared A chunks, L2-resident U).
// Each CTA loops 8 comps x 4 chunks through one warm 2-stage pipeline.
// ============================================================================
#define GW_A(buf)  ((buf) * 32768u)
#define GW_B(buf)  ((buf) * 32768u + 16384u)
#define GW_SMEM    65536
#define GW_NQQ     32     // 8 comps * 4 chunks

__global__ void __launch_bounds__(256, 2) wino_gemm_kernel()
{
    extern __shared__ char sm[];
    const uint32_t sb = smem_u32(sm);
    const int tid = threadIdx.x;
    const int mblk = blockIdx.x >> 3;
    const int n0 = ((blockIdx.x >> 1) & 3) << 7;   // n quarter: 0,128,256,384
    const int c0 = (blockIdx.x & 1) << 3;          // comp base: 0 or 8
    const int t0 = mblk << 7;

    // loads: A and B tiles both 128 rows x 128B; 2 thr/row, 4 x 16B each
    const int rowT = tid >> 1;
    const int kg0 = (tid & 1) * 4;
    const uint32_t swT = (uint32_t)(rowT & 7);

    // warp geometry: 8 warps = 2(m) x 4(n), warp tile 64x32
    const int w = tid >> 5, l = tid & 31;
    const int wm = (w >> 2) * 64, wn = (w & 3) * 32;
    const int lrow = l & 15, hi = l >> 4;
    const uint32_t swL = (uint32_t)(lrow & 7);
    uint32_t aRow[4], bRow[2];
    #pragma unroll
    for (int mt = 0; mt < 4; ++mt) aRow[mt] = (uint32_t)((wm + mt * 16 + lrow) * 128);
    #pragma unroll
    for (int nt = 0; nt < 2; ++nt) bRow[nt] = (uint32_t)((wn + nt * 16 + lrow) * 128);

    float acc[4][4][4];
    #pragma unroll
    for (int mt = 0; mt < 4; ++mt)
        #pragma unroll
        for (int n8 = 0; n8 < 4; ++n8)
            #pragma unroll
            for (int e = 0; e < 4; ++e) acc[mt][n8][e] = 0.0f;

    auto load_chunk = [&](int qq, int buf) {
        const int comp = c0 + (qq >> 2), q = qq & 3;
        const uint32_t Ab = sb + GW_A(buf), Bb = sb + GW_B(buf);
        const char* srcA = reinterpret_cast<const char*>(
            g_V + ((size_t)comp * NTIL + t0 + rowT) * 256 + q * 64);
        const char* srcB = reinterpret_cast<const char*>(
            g_wU + ((size_t)comp * 512 + n0 + rowT) * 256 + q * 64);
        #pragma unroll
        for (int i = 0; i < 4; ++i) {
            const int kg = kg0 + i;
            const uint32_t off = (uint32_t)rowT * 128 + (((uint32_t)kg ^ swT) << 4);
            CP_ASYNC16(Ab + off, srcA + kg * 16, 16);
            CP_ASYNC16(Bb + off, srcB + kg * 16, 16);
        }
    };

    load_chunk(0, 0);
    CP_COMMIT();

    const int qrow = l >> 2, qcol = (l & 3) * 2;

    #pragma unroll 1
    for (int qq = 0; qq < GW_NQQ; ++qq) {
        if (qq + 1 < GW_NQQ) {
            load_chunk(qq + 1, (qq + 1) & 1);
            CP_COMMIT();
            CP_WAIT1();
        } else {
            CP_WAIT0();
        }
        __syncthreads();

        const uint32_t Ab = sb + GW_A(qq & 1), Bb = sb + GW_B(qq & 1);
        #pragma unroll
        for (int ks = 0; ks < 4; ++ks) {
            const uint32_t col = (((uint32_t)(ks * 2 + hi)) ^ swL) << 4;
            uint32_t af[4][4], bf[2][4];
            #pragma unroll
            for (int mt = 0; mt < 4; ++mt) ldm4(af[mt], Ab + aRow[mt] + col);
            #pragma unroll
            for (int nt = 0; nt < 2; ++nt) ldm4(bf[nt], Bb + bRow[nt] + col);
            #pragma unroll
            for (int mt = 0; mt < 4; ++mt)
                #pragma unroll
                for (int n8 = 0; n8 < 4; ++n8)
                    mma16816(acc[mt][n8], af[mt], bf[n8 >> 1][n8 & 1], bf[n8 >> 1][(n8 & 1) + 2]);
        }
        __syncthreads();

        if ((qq & 3) == 3) {
            const int comp = c0 + (qq >> 2);
            __half* Mb = g_M + ((size_t)comp * NTIL + t0) * 512 + n0;
            #pragma unroll
            for (int mt = 0; mt < 4; ++mt) {
                #pragma unroll
                for (int n8 = 0; n8 < 4; ++n8) {
                    const int ch = wn + n8 * 8 + qcol;
                    #pragma unroll
                    for (int hlf = 0; hlf < 2; ++hlf) {
                        const int m = wm + mt * 16 + qrow + hlf * 8;
                        *reinterpret_cast<__half2*>(Mb + (size_t)m * 512 + ch) =
                            __floats2half2_rn(acc[mt][n8][2 * hlf], acc[mt][n8][2 * hlf + 1]);
                        acc[mt][n8][2 * hlf] = 0.0f;
                        acc[mt][n8][2 * hlf + 1] = 0.0f;
                    }
                }
            }
        }
    }
}

// ============================================================================
// Kernel 5: output transform Y = At M A + bias, relu6 -> g_sh (fp16 M input).
// ============================================================================
__global__ void wino_out_kernel(const float* __restrict__ bias) {
    const int t = blockIdx.x;
    const int n2 = threadIdx.x;             // n = 2*n2
    const int tw = t & 63, th = (t >> 6) & 63, b = t >> 12;

    float2 m[4][4];
    #pragma unroll
    for (int i = 0; i < 4; ++i)
        #pragma unroll
        for (int j = 0; j < 4; ++j) {
            __half2 hm = *reinterpret_cast<const __half2*>(
                g_M + ((size_t)(i * 4 + j) * NTIL + t) * 512 + 2 * n2);
            m[i][j] = __half22float2(hm);
        }

    float2 s[2][4];
    #pragma unroll
    for (int j = 0; j < 4; ++j) {
        s[0][j] = make_float2(m[0][j].x + m[1][j].x + m[2][j].x,
                              m[0][j].y + m[1][j].y + m[2][j].y);
        s[1][j] = make_float2(m[1][j].x - m[2][j].x - m[3][j].x,
                              m[1][j].y - m[2][j].y - m[3][j].y);
    }
    const float b0 = bias[2 * n2], b1 = bias[2 * n2 + 1];
    #pragma unroll
    for (int dy = 0; dy < 2; ++dy) {
        float2 y0 = make_float2(s[dy][0].x + s[dy][1].x + s[dy][2].x,
                                s[dy][0].y + s[dy][1].y + s[dy][2].y);
        float2 y1 = make_float2(s[dy][1].x - s[dy][2].x - s[dy][3].x,
                                s[dy][1].y - s[dy][2].y - s[dy][3].y);
        const int h = 2 * th + dy;
        #pragma unroll
        for (int dx = 0; dx < 2; ++dx) {
            const float2 yv = dx ? y1 : y0;
            float v0 = fminf(fmaxf(yv.x + b0, 0.0f), 6.0f);
            float v1 = fminf(fmaxf(yv.y + b1, 0.0f), 6.0f);
            const int w_ = 2 * tw + dx;
            *reinterpret_cast<__half2*>(
                g_sh + ((size_t)((b * 128 + h) * 128 + w_)) * 512 + 2 * n2) =
                __floats2half2_rn(v0, v1);
        }
    }
}

// ============================================================================
// Kernel 6: head GEMM M=128/N=128(96 used)/K=512 + bias + softmax + writes.
// ============================================================================
#define HD_A(buf)  ((buf) * 32768u)
#define HD_B(buf)  ((buf) * 32768u + 16384u)
#define HD_BIAS    65536u
#define HD_SMEM    66048
#define HD_NCH     8

__global__ void __launch_bounds__(256, 1) head_kernel(const float* __restrict__ bc,
                                                      const float* __restrict__ br,
                                                      float* __restrict__ out)
{
    extern __shared__ char sm[];
    const uint32_t sb = smem_u32(sm);
    const int tid = threadIdx.x;
    const size_t pos0 = (size_t)blockIdx.x * 128;

    float* hb = reinterpret_cast<float*>(sm + HD_BIAS);
    if (tid < 128)
        hb[tid] = (tid < 30) ? bc[tid] : (tid < 90 ? br[tid - 30] : 0.0f);

    const int rowT = tid >> 1;
    const int kg0 = (tid * 4) & 7;
    const uint32_t swT = (uint32_t)(rowT & 7);

    const int w = tid >> 5, l = tid & 31;
    const int wm = (w >> 2) * 64, wn = (w & 3) * 32;
    const int lrow = l & 15, hi = l >> 4;
    const uint32_t swL = (uint32_t)(lrow & 7);
    uint32_t aRow[4], bRow[2];
    #pragma unroll
    for (int mt = 0; mt < 4; ++mt) aRow[mt] = (uint32_t)((wm + mt * 16 + lrow) * 128);
    #pragma unroll
    for (int nt = 0; nt < 2; ++nt) bRow[nt] = (uint32_t)((wn + nt * 16 + lrow) * 128);

    float acc[4][4][4];
    #pragma unroll
    for (int mt = 0; mt < 4; ++mt)
        #pragma unroll
        for (int n8 = 0; n8 < 4; ++n8)
            #pragma unroll
            for (int e = 0; e < 4; ++e) acc[mt][n8][e] = 0.0f;

    auto load_chunk = [&](int q, int buf) {
        const uint32_t Ab = sb + HD_A(buf), Bb = sb + HD_B(buf);
        const char* srcA = reinterpret_cast<const char*>(
            g_sh + (pos0 + rowT) * 512 + q * 64);
        const char* srcB = reinterpret_cast<const char*>(
            g_wh + (size_t)rowT * 512 + q * 64);
        #pragma unroll
        for (int i = 0; i < 4; ++i) {
            const int kg = kg0 + i;
            const uint32_t off = (uint32_t)rowT * 128 + (((uint32_t)kg ^ swT) << 4);
            CP_ASYNC16(Ab + off, srcA + kg * 16, 16);
            CP_ASYNC16(Bb + off, srcB + kg * 16, 16);
        }
    };

    load_chunk(0, 0);
    CP_COMMIT();

    #pragma unroll 1
    for (int q = 0; q < HD_NCH; ++q) {
        if (q + 1 < HD_NCH) {
            load_chunk(q + 1, (q + 1) & 1);
            CP_COMMIT();
            CP_WAIT1();
        } else {
            CP_WAIT0();
        }
        __syncthreads();

        const uint32_t Ab = sb + HD_A(q & 1), Bb = sb + HD_B(q & 1);
        #pragma unroll
        for (int ks = 0; ks < 4; ++ks) {
            const uint32_t col = (((uint32_t)(ks * 2 + hi)) ^ swL) << 4;
            uint32_t af[4][4], bf[2][4];
            #pragma unroll
            for (int mt = 0; mt < 4; ++mt) ldm4(af[mt], Ab + aRow[mt] + col);
            #pragma unroll
            for (int nt = 0; nt < 2; ++nt) ldm4(bf[nt], Bb + bRow[nt] + col);
            #pragma unroll
            for (int mt = 0; mt < 4; ++mt)
                #pragma unroll
                for (int n8 = 0; n8 < 4; ++n8)
                    mma16816(acc[mt][n8], af[mt], bf[n8 >> 1][n8 & 1], bf[n8 >> 1][(n8 & 1) + 2]);
        }
        __syncthreads();
    }

    const int qrow = l >> 2, qcol = (l & 3) * 2;
    #pragma unroll
    for (int mt = 0; mt < 4; ++mt) {
        #pragma unroll
        for (int n8 = 0; n8 < 4; ++n8) {
            const int ch = wn + n8 * 8 + qcol;
            if (ch >= 90) continue;
            const float b0 = hb[ch], b1 = hb[ch + 1];
            #pragma unroll
            for (int hlf = 0; hlf < 2; ++hlf) {
                const int m = wm + mt * 16 + qrow + hlf * 8;
                const size_t pos = pos0 + m;
                const float v0 = acc[mt][n8][2 * hlf]     + b0;
                const float v1 = acc[mt][n8][2 * hlf + 1] + b1;
                if (ch < 30) {
                    *reinterpret_cast<float2*>(out + pos * 30 + ch) = make_float2(v0, v1);
                    const float mx = fmaxf(v0, v1);
                    const float e0 = __expf(v0 - mx), e1 = __expf(v1 - mx);
                    const float inv = 1.0f / (e0 + e1);
                    *reinterpret_cast<float2*>(out + OFF_PROBS + pos * 30 + ch) =
                        make_float2(e0 * inv, e1 * inv);
                } else {
                    *reinterpret_cast<float2*>(out + OFF_DELTAS + pos * 60 + (ch - 30)) =
                        make_float2(v0, v1);
                }
            }
        }
    }
}

// ============================================================================
// Launch
// ============================================================================
extern "C" void kernel_launch(void* const* d_in, const int* in_sizes, int n_in,
                              void* d_out, int out_size) {
    const float* x  = (const float*)d_in[0];
    const float* ws = (const float*)d_in[1];
    const float* bs = (const float*)d_in[2];
    const float* wc = (const float*)d_in[3];
    const float* bc = (const float*)d_in[4];
    const float* wr = (const float*)d_in[5];
    const float* br = (const float*)d_in[6];
    float* out = (float*)d_out;

    cudaFuncSetAttribute(wino_gemm_kernel, cudaFuncAttributeMaxDynamicSharedMemorySize, GW_SMEM);
    cudaFuncSetAttribute(head_kernel, cudaFuncAttributeMaxDynamicSharedMemorySize, HD_SMEM);

    wino_in_kernel<<<NTIL, 128>>>(x);
    wino_w_kernel<<<512, 256>>>(ws);
    cvt_wh_kernel<<<128, 512>>>(wc, wr);
    wino_gemm_kernel<<<2048, 256, GW_SMEM>>>();
    wino_out_kernel<<<NTIL, 256>>>(bs);
    head_kernel<<<1024, 256, HD_SMEM>>>(bc, br, out);
}

// round 10
// speedup vs baseline: 1.5219x; 1.5219x over previous
#include <cuda_runtime.h>
#include <cuda_fp16.h>
#include <cstdint>

// ============================================================================
// RPNHead via Winograd F(2x2,3x3). R10: GEMM back to R8 shape (512thr/16w/
// 128x256) with a 3-stage cp.async pipeline and ONE barrier per chunk.
// Head re-tiled to 512thr/16w CTA 256x128 with the same proven geometry.
// ============================================================================
#define NPOS 131072
#define NTIL 32768
#define OFF_PROBS  3932160
#define OFF_DELTAS 7864320

__device__ __align__(1024) __half g_V [(size_t)16*NTIL*256];   // input transform
__device__ __align__(1024) __half g_wU[(size_t)16*512*256];    // weight transform
__device__ __align__(1024) __half g_M [(size_t)16*NTIL*512];   // GEMM results (fp16)
__device__ __align__(1024) __half g_sh[(size_t)NPOS*512];      // shared acts fp16
__device__ __align__(1024) __half g_wh[(size_t)128*512];       // head W [j][c]

__device__ __forceinline__ uint32_t smem_u32(const void* p) {
    uint32_t a;
    asm("{ .reg .u64 t; cvta.to.shared.u64 t, %1; cvt.u32.u64 %0, t; }"
        : "=r"(a) : "l"(p));
    return a;
}

#define CP_ASYNC16(dst, src, sz) \
    asm volatile("cp.async.cg.shared.global [%0], [%1], 16, %2;" \
        :: "r"((uint32_t)(dst)), "l"(src), "r"((int)(sz)) : "memory")
#define CP_COMMIT() asm volatile("cp.async.commit_group;" ::: "memory")
#define CP_WAIT1()  asm volatile("cp.async.wait_group 1;" ::: "memory")
#define CP_WAIT0()  asm volatile("cp.async.wait_group 0;" ::: "memory")

__device__ __forceinline__ void ldm4(uint32_t* f, uint32_t addr) {
    asm volatile("ldmatrix.sync.aligned.m8n8.x4.shared.b16 {%0,%1,%2,%3}, [%4];"
        : "=r"(f[0]), "=r"(f[1]), "=r"(f[2]), "=r"(f[3]) : "r"(addr));
}
__device__ __forceinline__ void mma16816(float* c, const uint32_t* a,
                                         uint32_t b0, uint32_t b1) {
    asm volatile("mma.sync.aligned.m16n8k16.row.col.f32.f16.f16.f32 "
        "{%0,%1,%2,%3}, {%4,%5,%6,%7}, {%8,%9}, {%0,%1,%2,%3};"
        : "+f"(c[0]), "+f"(c[1]), "+f"(c[2]), "+f"(c[3])
        : "r"(a[0]), "r"(a[1]), "r"(a[2]), "r"(a[3]), "r"(b0), "r"(b1));
}

// ============================================================================
// Kernel 1: input transform V = Bt d B (fp32 x -> fp16 V).
// ============================================================================
__global__ void wino_in_kernel(const float* __restrict__ x) {
    const int t = blockIdx.x;
    const int c2 = threadIdx.x;                 // channel pair
    const int tw = t & 63, th = (t >> 6) & 63, b = t >> 12;
    const int h0 = th * 2 - 1, w0 = tw * 2 - 1;

    float2 d[4][4];
    #pragma unroll
    for (int i = 0; i < 4; ++i) {
        const int h = h0 + i;
        const bool hv = (h >= 0) && (h < 128);
        #pragma unroll
        for (int j = 0; j < 4; ++j) {
            const int w_ = w0 + j;
            if (hv && w_ >= 0 && w_ < 128)
                d[i][j] = *reinterpret_cast<const float2*>(
                    x + ((size_t)((b * 128 + h) * 128 + w_)) * 256 + 2 * c2);
            else
                d[i][j] = make_float2(0.0f, 0.0f);
        }
    }
    float2 tr[4][4];
    #pragma unroll
    for (int j = 0; j < 4; ++j) {
        tr[0][j] = make_float2(d[0][j].x - d[2][j].x, d[0][j].y - d[2][j].y);
        tr[1][j] = make_float2(d[1][j].x + d[2][j].x, d[1][j].y + d[2][j].y);
        tr[2][j] = make_float2(d[2][j].x - d[1][j].x, d[2][j].y - d[1][j].y);
        tr[3][j] = make_float2(d[1][j].x - d[3][j].x, d[1][j].y - d[3][j].y);
    }
    #pragma unroll
    for (int i = 0; i < 4; ++i) {
        float2 v0 = make_float2(tr[i][0].x - tr[i][2].x, tr[i][0].y - tr[i][2].y);
        float2 v1 = make_float2(tr[i][1].x + tr[i][2].x, tr[i][1].y + tr[i][2].y);
        float2 v2 = make_float2(tr[i][2].x - tr[i][1].x, tr[i][2].y - tr[i][1].y);
        float2 v3 = make_float2(tr[i][1].x - tr[i][3].x, tr[i][1].y - tr[i][3].y);
        *reinterpret_cast<__half2*>(g_V + ((size_t)(i*4+0)*NTIL + t)*256 + 2*c2) = __floats2half2_rn(v0.x, v0.y);
        *reinterpret_cast<__half2*>(g_V + ((size_t)(i*4+1)*NTIL + t)*256 + 2*c2) = __floats2half2_rn(v1.x, v1.y);
        *reinterpret_cast<__half2*>(g_V + ((size_t)(i*4+2)*NTIL + t)*256 + 2*c2) = __floats2half2_rn(v2.x, v2.y);
        *reinterpret_cast<__half2*>(g_V + ((size_t)(i*4+3)*NTIL + t)*256 + 2*c2) = __floats2half2_rn(v3.x, v3.y);
    }
}

// ============================================================================
// Kernel 2: weight transform U = G g Gt. grid=512 (n), block=256 (c).
// ============================================================================
__global__ void wino_w_kernel(const float* __restrict__ ws) {
    const int n = blockIdx.x;
    const int c = threadIdx.x;
    float g[3][3];
    #pragma unroll
    for (int kh = 0; kh < 3; ++kh)
        #pragma unroll
        for (int kw = 0; kw < 3; ++kw)
            g[kh][kw] = ws[((size_t)(kh * 3 + kw) * 256 + c) * 512 + n];
    float u[4][3];
    #pragma unroll
    for (int kw = 0; kw < 3; ++kw) {
        u[0][kw] = g[0][kw];
        u[1][kw] = 0.5f * (g[0][kw] + g[1][kw] + g[2][kw]);
        u[2][kw] = 0.5f * (g[0][kw] - g[1][kw] + g[2][kw]);
        u[3][kw] = g[2][kw];
    }
    #pragma unroll
    for (int r = 0; r < 4; ++r) {
        float U0 = u[r][0];
        float U1 = 0.5f * (u[r][0] + u[r][1] + u[r][2]);
        float U2 = 0.5f * (u[r][0] - u[r][1] + u[r][2]);
        float U3 = u[r][2];
        g_wU[((size_t)(r * 4 + 0) * 512 + n) * 256 + c] = __float2half(U0);
        g_wU[((size_t)(r * 4 + 1) * 512 + n) * 256 + c] = __float2half(U1);
        g_wU[((size_t)(r * 4 + 2) * 512 + n) * 256 + c] = __float2half(U2);
        g_wU[((size_t)(r * 4 + 3) * 512 + n) * 256 + c] = __float2half(U3);
    }
}

// ============================================================================
// Kernel 3: head weight pack.
// ============================================================================
__global__ void cvt_wh_kernel(const float* __restrict__ wc, const float* __restrict__ wr) {
    const int j = blockIdx.x;    // 0..127
    const int c = threadIdx.x;   // 0..511
    float v = 0.0f;
    if (j < 30)      v = wc[c * 30 + j];
    else if (j < 90) v = wr[c * 60 + (j - 30)];
    g_wh[(size_t)j * 512 + c] = __float2half(v);
}

// ============================================================================
// Kernel 4: persistent batched GEMM (R8 config + 3-stage single-sync pipe).
// grid = 1024: mblk(256) x nhalf(2) x chalf(2). 512 thr, 16 warps (2m x 8n),
// warp 64x32, CTA 128x256. 8 comps x 4 chunks per CTA.
// SMEM: 3 stages x (16KB A + 32KB B) = 144KB.
// ============================================================================
#define GW_STG     49152u
#define GW_A(s)    ((s) * GW_STG)
#define GW_B(s)    ((s) * GW_STG + 16384u)
#define GW_SMEM    147456
#define GW_NQQ     32

__global__ void __launch_bounds__(512, 1) wino_gemm_kernel()
{
    extern __shared__ char sm[];
    const uint32_t sb = smem_u32(sm);
    const int tid = threadIdx.x;
    const int mblk = blockIdx.x >> 2;
    const int n0 = ((blockIdx.x >> 1) & 1) << 8;
    const int c0 = (blockIdx.x & 1) << 3;
    const int t0 = mblk << 7;

    const int rowA = tid >> 2;
    const int kgA0 = (tid * 2) & 7;
    const int rowB = tid >> 1;
    const int kgB0 = (tid * 4) & 7;
    const uint32_t swA = (uint32_t)(rowA & 7);
    const uint32_t swB = (uint32_t)(rowB & 7);

    const int w = tid >> 5, l = tid & 31;
    const int wm = (w >> 3) * 64, wn = (w & 7) * 32;
    const int lrow = l & 15, hi = l >> 4;
    const uint32_t swL = (uint32_t)(lrow & 7);
    uint32_t aRow[4], bRow[2];
    #pragma unroll
    for (int mt = 0; mt < 4; ++mt) aRow[mt] = (uint32_t)((wm + mt * 16 + lrow) * 128);
    #pragma unroll
    for (int nt = 0; nt < 2; ++nt) bRow[nt] = (uint32_t)((wn + nt * 16 + lrow) * 128);

    float acc[4][4][4];
    #pragma unroll
    for (int mt = 0; mt < 4; ++mt)
        #pragma unroll
        for (int n8 = 0; n8 < 4; ++n8)
            #pragma unroll
            for (int e = 0; e < 4; ++e) acc[mt][n8][e] = 0.0f;

    auto load_chunk = [&](int qq, int s) {
        const int comp = c0 + (qq >> 2), q = qq & 3;
        const uint32_t Ab = sb + GW_A(s), Bb = sb + GW_B(s);
        const char* srcA = reinterpret_cast<const char*>(
            g_V + ((size_t)comp * NTIL + t0 + rowA) * 256 + q * 64);
        #pragma unroll
        for (int i = 0; i < 2; ++i) {
            const int kg = kgA0 + i;
            CP_ASYNC16(Ab + (uint32_t)rowA * 128 + (((uint32_t)kg ^ swA) << 4),
                       srcA + kg * 16, 16);
        }
        const char* srcB = reinterpret_cast<const char*>(
            g_wU + ((size_t)comp * 512 + n0 + rowB) * 256 + q * 64);
        #pragma unroll
        for (int i = 0; i < 4; ++i) {
            const int kg = kgB0 + i;
            CP_ASYNC16(Bb + (uint32_t)rowB * 128 + (((uint32_t)kg ^ swB) << 4),
                       srcB + kg * 16, 16);
        }
    };

    load_chunk(0, 0); CP_COMMIT();
    load_chunk(1, 1); CP_COMMIT();

    const int qrow = l >> 2, qcol = (l & 3) * 2;

    #pragma unroll 1
    for (int qq = 0; qq < GW_NQQ; ++qq) {
        if (qq + 1 < GW_NQQ) CP_WAIT1(); else CP_WAIT0();
        __syncthreads();
        if (qq + 2 < GW_NQQ) { load_chunk(qq + 2, (qq + 2) % 3); CP_COMMIT(); }

        const uint32_t Ab = sb + GW_A(qq % 3), Bb = sb + GW_B(qq % 3);
        #pragma unroll
        for (int ks = 0; ks < 4; ++ks) {
            const uint32_t col = (((uint32_t)(ks * 2 + hi)) ^ swL) << 4;
            uint32_t af[4][4], bf[2][4];
            #pragma unroll
            for (int mt = 0; mt < 4; ++mt) ldm4(af[mt], Ab + aRow[mt] + col);
            #pragma unroll
            for (int nt = 0; nt < 2; ++nt) ldm4(bf[nt], Bb + bRow[nt] + col);
            #pragma unroll
            for (int mt = 0; mt < 4; ++mt)
                #pragma unroll
                for (int n8 = 0; n8 < 4; ++n8)
                    mma16816(acc[mt][n8], af[mt], bf[n8 >> 1][n8 & 1], bf[n8 >> 1][(n8 & 1) + 2]);
        }

        if ((qq & 3) == 3) {
            const int comp = c0 + (qq >> 2);
            __half* Mb = g_M + ((size_t)comp * NTIL + t0) * 512 + n0;
            #pragma unroll
            for (int mt = 0; mt < 4; ++mt) {
                #pragma unroll
                for (int n8 = 0; n8 < 4; ++n8) {
                    const int ch = wn + n8 * 8 + qcol;
                    #pragma unroll
                    for (int hlf = 0; hlf < 2; ++hlf) {
                        const int m = wm + mt * 16 + qrow + hlf * 8;
                        *reinterpret_cast<__half2*>(Mb + (size_t)m * 512 + ch) =
                            __floats2half2_rn(acc[mt][n8][2 * hlf], acc[mt][n8][2 * hlf + 1]);
                        acc[mt][n8][2 * hlf] = 0.0f;
                        acc[mt][n8][2 * hlf + 1] = 0.0f;
                    }
                }
            }
        }
    }
}

// ============================================================================
// Kernel 5: output transform Y = At M A + bias, relu6 -> g_sh (fp16 M input).
// ============================================================================
__global__ void wino_out_kernel(const float* __restrict__ bias) {
    const int t = blockIdx.x;
    const int n2 = threadIdx.x;             // n = 2*n2
    const int tw = t & 63, th = (t >> 6) & 63, b = t >> 12;

    float2 m[4][4];
    #pragma unroll
    for (int i = 0; i < 4; ++i)
        #pragma unroll
        for (int j = 0; j < 4; ++j) {
            __half2 hm = *reinterpret_cast<const __half2*>(
                g_M + ((size_t)(i * 4 + j) * NTIL + t) * 512 + 2 * n2);
            m[i][j] = __half22float2(hm);
        }

    float2 s[2][4];
    #pragma unroll
    for (int j = 0; j < 4; ++j) {
        s[0][j] = make_float2(m[0][j].x + m[1][j].x + m[2][j].x,
                              m[0][j].y + m[1][j].y + m[2][j].y);
        s[1][j] = make_float2(m[1][j].x - m[2][j].x - m[3][j].x,
                              m[1][j].y - m[2][j].y - m[3][j].y);
    }
    const float b0 = bias[2 * n2], b1 = bias[2 * n2 + 1];
    #pragma unroll
    for (int dy = 0; dy < 2; ++dy) {
        float2 y0 = make_float2(s[dy][0].x + s[dy][1].x + s[dy][2].x,
                                s[dy][0].y + s[dy][1].y + s[dy][2].y);
        float2 y1 = make_float2(s[dy][1].x - s[dy][2].x - s[dy][3].x,
                                s[dy][1].y - s[dy][2].y - s[dy][3].y);
        const int h = 2 * th + dy;
        #pragma unroll
        for (int dx = 0; dx < 2; ++dx) {
            const float2 yv = dx ? y1 : y0;
            float v0 = fminf(fmaxf(yv.x + b0, 0.0f), 6.0f);
            float v1 = fminf(fmaxf(yv.y + b1, 0.0f), 6.0f);
            const int w_ = 2 * tw + dx;
            *reinterpret_cast<__half2*>(
                g_sh + ((size_t)((b * 128 + h) * 128 + w_)) * 512 + 2 * n2) =
                __floats2half2_rn(v0, v1);
        }
    }
}

// ============================================================================
// Kernel 6: head GEMM, re-tiled: CTA 256(M)x128(N), 512 thr, 16 warps (4m x 4n),
// warp 64x32, K=512 in 8 chunks, 3-stage single-sync pipeline.
// SMEM: 3 x (32KB A + 16KB B) = 144KB + 512B bias.
// grid = 512.
// ============================================================================
#define HD_STG     49152u
#define HD_A(s)    ((s) * HD_STG)
#define HD_B(s)    ((s) * HD_STG + 32768u)
#define HD_BIAS    147456u
#define HD_SMEM    147968
#define HD_NQQ     8

__global__ void __launch_bounds__(512, 1) head_kernel(const float* __restrict__ bc,
                                                      const float* __restrict__ br,
                                                      float* __restrict__ out)
{
    extern __shared__ char sm[];
    const uint32_t sb = smem_u32(sm);
    const int tid = threadIdx.x;
    const size_t pos0 = (size_t)blockIdx.x * 256;

    float* hb = reinterpret_cast<float*>(sm + HD_BIAS);
    if (tid < 128)
        hb[tid] = (tid < 30) ? bc[tid] : (tid < 90 ? br[tid - 30] : 0.0f);

    // A: 256 rows x 128B, 2 thr/row, 4 x 16B each
    const int rowA = tid >> 1;
    const int kgA0 = (tid & 1) * 4;
    const uint32_t swA = (uint32_t)(rowA & 7);
    // B: 128 rows x 128B, 4 thr/row, 2 x 16B each
    const int rowB = tid >> 2;
    const int kgB0 = (tid & 3) * 2;
    const uint32_t swB = (uint32_t)(rowB & 7);

    // 16 warps = 4(m) x 4(n), warp tile 64x32
    const int w = tid >> 5, l = tid & 31;
    const int wm = (w >> 2) * 64, wn = (w & 3) * 32;
    const int lrow = l & 15, hi = l >> 4;
    const uint32_t swL = (uint32_t)(lrow & 7);
    uint32_t aRow[4], bRow[2];
    #pragma unroll
    for (int mt = 0; mt < 4; ++mt) aRow[mt] = (uint32_t)((wm + mt * 16 + lrow) * 128);
    #pragma unroll
    for (int nt = 0; nt < 2; ++nt) bRow[nt] = (uint32_t)((wn + nt * 16 + lrow) * 128);

    float acc[4][4][4];
    #pragma unroll
    for (int mt = 0; mt < 4; ++mt)
        #pragma unroll
        for (int n8 = 0; n8 < 4; ++n8)
            #pragma unroll
            for (int e = 0; e < 4; ++e) acc[mt][n8][e] = 0.0f;

    auto load_chunk = [&](int q, int s) {
        const uint32_t Ab = sb + HD_A(s), Bb = sb + HD_B(s);
        const char* srcA = reinterpret_cast<const char*>(
            g_sh + (pos0 + rowA) * 512 + q * 64);
        #pragma unroll
        for (int i = 0; i < 4; ++i) {
            const int kg = kgA0 + i;
            CP_ASYNC16(Ab + (uint32_t)rowA * 128 + (((uint32_t)kg ^ swA) << 4),
                       srcA + kg * 16, 16);
        }
        const char* srcB = reinterpret_cast<const char*>(
            g_wh + (size_t)rowB * 512 + q * 64);
        #pragma unroll
        for (int i = 0; i < 2; ++i) {
            const int kg = kgB0 + i;
            CP_ASYNC16(Bb + (uint32_t)rowB * 128 + (((uint32_t)kg ^ swB) << 4),
                       srcB + kg * 16, 16);
        }
    };

    load_chunk(0, 0); CP_COMMIT();
    load_chunk(1, 1); CP_COMMIT();

    #pragma unroll 1
    for (int q = 0; q < HD_NQQ; ++q) {
        if (q + 1 < HD_NQQ) CP_WAIT1(); else CP_WAIT0();
        __syncthreads();
        if (q + 2 < HD_NQQ) { load_chunk(q + 2, (q + 2) % 3); CP_COMMIT(); }

        const uint32_t Ab = sb + HD_A(q % 3), Bb = sb + HD_B(q % 3);
        #pragma unroll
        for (int ks = 0; ks < 4; ++ks) {
            const uint32_t col = (((uint32_t)(ks * 2 + hi)) ^ swL) << 4;
            uint32_t af[4][4], bf[2][4];
            #pragma unroll
            for (int mt = 0; mt < 4; ++mt) ldm4(af[mt], Ab + aRow[mt] + col);
            #pragma unroll
            for (int nt = 0; nt < 2; ++nt) ldm4(bf[nt], Bb + bRow[nt] + col);
            #pragma unroll
            for (int mt = 0; mt < 4; ++mt)
                #pragma unroll
                for (int n8 = 0; n8 < 4; ++n8)
                    mma16816(acc[mt][n8], af[mt], bf[n8 >> 1][n8 & 1], bf[n8 >> 1][(n8 & 1) + 2]);
        }
    }

    const int qrow = l >> 2, qcol = (l & 3) * 2;
    #pragma unroll
    for (int mt = 0; mt < 4; ++mt) {
        #pragma unroll
        for (int n8 = 0; n8 < 4; ++n8) {
            const int ch = wn + n8 * 8 + qcol;
            if (ch >= 90) continue;
            const float b0 = hb[ch], b1 = hb[ch + 1];
            #pragma unroll
            for (int hlf = 0; hlf < 2; ++hlf) {
                const int m = wm + mt * 16 + qrow + hlf * 8;
                const size_t pos = pos0 + m;
                const float v0 = acc[mt][n8][2 * hlf]     + b0;
                const float v1 = acc[mt][n8][2 * hlf + 1] + b1;
                if (ch < 30) {
                    *reinterpret_cast<float2*>(out + pos * 30 + ch) = make_float2(v0, v1);
                    const float mx = fmaxf(v0, v1);
                    const float e0 = __expf(v0 - mx), e1 = __expf(v1 - mx);
                    const float inv = 1.0f / (e0 + e1);
                    *reinterpret_cast<float2*>(out + OFF_PROBS + pos * 30 + ch) =
                        make_float2(e0 * inv, e1 * inv);
                } else {
                    *reinterpret_cast<float2*>(out + OFF_DELTAS + pos * 60 + (ch - 30)) =
                        make_float2(v0, v1);
                }
            }
        }
    }
}

// ============================================================================
// Launch
// ============================================================================
extern "C" void kernel_launch(void* const* d_in, const int* in_sizes, int n_in,
                              void* d_out, int out_size) {
    const float* x  = (const float*)d_in[0];
    const float* ws = (const float*)d_in[1];
    const float* bs = (const float*)d_in[2];
    const float* wc = (const float*)d_in[3];
    const float* bc = (const float*)d_in[4];
    const float* wr = (const float*)d_in[5];
    const float* br = (const float*)d_in[6];
    float* out = (float*)d_out;

    cudaFuncSetAttribute(wino_gemm_kernel, cudaFuncAttributeMaxDynamicSharedMemorySize, GW_SMEM);
    cudaFuncSetAttribute(head_kernel, cudaFuncAttributeMaxDynamicSharedMemorySize, HD_SMEM);

    wino_in_kernel<<<NTIL, 128>>>(x);
    wino_w_kernel<<<512, 256>>>(ws);
    cvt_wh_kernel<<<128, 512>>>(wc, wr);
    wino_gemm_kernel<<<1024, 512, GW_SMEM>>>();
    wino_out_kernel<<<NTIL, 256>>>(bs);
    head_kernel<<<512, 512, HD_SMEM>>>(bc, br, out);
}

// round 12
// speedup vs baseline: 1.5657x; 1.0288x over previous
#include <cuda_runtime.h>
#include <cuda_fp16.h>
#include <cstdint>

// ============================================================================
// RPNHead via Winograd F(2x2,3x3). R12: GEMM = R10 verbatim (3-stage,
// single-barrier, proven 565us). Head = R8's proven 256-thread kernel with
// warp N-tile trimmed 32->24 (skip the padded cols 96..127; loaders and
// smem layout unchanged).
// ============================================================================
#define NPOS 131072
#define NTIL 32768
#define OFF_PROBS  3932160
#define OFF_DELTAS 7864320

__device__ __align__(1024) __half g_V [(size_t)16*NTIL*256];   // input transform
__device__ __align__(1024) __half g_wU[(size_t)16*512*256];    // weight transform
__device__ __align__(1024) __half g_M [(size_t)16*NTIL*512];   // GEMM results (fp16)
__device__ __align__(1024) __half g_sh[(size_t)NPOS*512];      // shared acts fp16
__device__ __align__(1024) __half g_wh[(size_t)128*512];       // head W [j][c]

__device__ __forceinline__ uint32_t smem_u32(const void* p) {
    uint32_t a;
    asm("{ .reg .u64 t; cvta.to.shared.u64 t, %1; cvt.u32.u64 %0, t; }"
        : "=r"(a) : "l"(p));
    return a;
}

#define CP_ASYNC16(dst, src, sz) \
    asm volatile("cp.async.cg.shared.global [%0], [%1], 16, %2;" \
        :: "r"((uint32_t)(dst)), "l"(src), "r"((int)(sz)) : "memory")
#define CP_COMMIT() asm volatile("cp.async.commit_group;" ::: "memory")
#define CP_WAIT1()  asm volatile("cp.async.wait_group 1;" ::: "memory")
#define CP_WAIT0()  asm volatile("cp.async.wait_group 0;" ::: "memory")

__device__ __forceinline__ void ldm4(uint32_t* f, uint32_t addr) {
    asm volatile("ldmatrix.sync.aligned.m8n8.x4.shared.b16 {%0,%1,%2,%3}, [%4];"
        : "=r"(f[0]), "=r"(f[1]), "=r"(f[2]), "=r"(f[3]) : "r"(addr));
}
__device__ __forceinline__ void mma16816(float* c, const uint32_t* a,
                                         uint32_t b0, uint32_t b1) {
    asm volatile("mma.sync.aligned.m16n8k16.row.col.f32.f16.f16.f32 "
        "{%0,%1,%2,%3}, {%4,%5,%6,%7}, {%8,%9}, {%0,%1,%2,%3};"
        : "+f"(c[0]), "+f"(c[1]), "+f"(c[2]), "+f"(c[3])
        : "r"(a[0]), "r"(a[1]), "r"(a[2]), "r"(a[3]), "r"(b0), "r"(b1));
}

// ============================================================================
// Kernel 1: input transform V = Bt d B (fp32 x -> fp16 V).
// ============================================================================
__global__ void wino_in_kernel(const float* __restrict__ x) {
    const int t = blockIdx.x;
    const int c2 = threadIdx.x;                 // channel pair
    const int tw = t & 63, th = (t >> 6) & 63, b = t >> 12;
    const int h0 = th * 2 - 1, w0 = tw * 2 - 1;

    float2 d[4][4];
    #pragma unroll
    for (int i = 0; i < 4; ++i) {
        const int h = h0 + i;
        const bool hv = (h >= 0) && (h < 128);
        #pragma unroll
        for (int j = 0; j < 4; ++j) {
            const int w_ = w0 + j;
            if (hv && w_ >= 0 && w_ < 128)
                d[i][j] = *reinterpret_cast<const float2*>(
                    x + ((size_t)((b * 128 + h) * 128 + w_)) * 256 + 2 * c2);
            else
                d[i][j] = make_float2(0.0f, 0.0f);
        }
    }
    float2 tr[4][4];
    #pragma unroll
    for (int j = 0; j < 4; ++j) {
        tr[0][j] = make_float2(d[0][j].x - d[2][j].x, d[0][j].y - d[2][j].y);
        tr[1][j] = make_float2(d[1][j].x + d[2][j].x, d[1][j].y + d[2][j].y);
        tr[2][j] = make_float2(d[2][j].x - d[1][j].x, d[2][j].y - d[1][j].y);
        tr[3][j] = make_float2(d[1][j].x - d[3][j].x, d[1][j].y - d[3][j].y);
    }
    #pragma unroll
    for (int i = 0; i < 4; ++i) {
        float2 v0 = make_float2(tr[i][0].x - tr[i][2].x, tr[i][0].y - tr[i][2].y);
        float2 v1 = make_float2(tr[i][1].x + tr[i][2].x, tr[i][1].y + tr[i][2].y);
        float2 v2 = make_float2(tr[i][2].x - tr[i][1].x, tr[i][2].y - tr[i][1].y);
        float2 v3 = make_float2(tr[i][1].x - tr[i][3].x, tr[i][1].y - tr[i][3].y);
        *reinterpret_cast<__half2*>(g_V + ((size_t)(i*4+0)*NTIL + t)*256 + 2*c2) = __floats2half2_rn(v0.x, v0.y);
        *reinterpret_cast<__half2*>(g_V + ((size_t)(i*4+1)*NTIL + t)*256 + 2*c2) = __floats2half2_rn(v1.x, v1.y);
        *reinterpret_cast<__half2*>(g_V + ((size_t)(i*4+2)*NTIL + t)*256 + 2*c2) = __floats2half2_rn(v2.x, v2.y);
        *reinterpret_cast<__half2*>(g_V + ((size_t)(i*4+3)*NTIL + t)*256 + 2*c2) = __floats2half2_rn(v3.x, v3.y);
    }
}

// ============================================================================
// Kernel 2: weight transform U = G g Gt. grid=512 (n), block=256 (c).
// ============================================================================
__global__ void wino_w_kernel(const float* __restrict__ ws) {
    const int n = blockIdx.x;
    const int c = threadIdx.x;
    float g[3][3];
    #pragma unroll
    for (int kh = 0; kh < 3; ++kh)
        #pragma unroll
        for (int kw = 0; kw < 3; ++kw)
            g[kh][kw] = ws[((size_t)(kh * 3 + kw) * 256 + c) * 512 + n];
    float u[4][3];
    #pragma unroll
    for (int kw = 0; kw < 3; ++kw) {
        u[0][kw] = g[0][kw];
        u[1][kw] = 0.5f * (g[0][kw] + g[1][kw] + g[2][kw]);
        u[2][kw] = 0.5f * (g[0][kw] - g[1][kw] + g[2][kw]);
        u[3][kw] = g[2][kw];
    }
    #pragma unroll
    for (int r = 0; r < 4; ++r) {
        float U0 = u[r][0];
        float U1 = 0.5f * (u[r][0] + u[r][1] + u[r][2]);
        float U2 = 0.5f * (u[r][0] - u[r][1] + u[r][2]);
        float U3 = u[r][2];
        g_wU[((size_t)(r * 4 + 0) * 512 + n) * 256 + c] = __float2half(U0);
        g_wU[((size_t)(r * 4 + 1) * 512 + n) * 256 + c] = __float2half(U1);
        g_wU[((size_t)(r * 4 + 2) * 512 + n) * 256 + c] = __float2half(U2);
        g_wU[((size_t)(r * 4 + 3) * 512 + n) * 256 + c] = __float2half(U3);
    }
}

// ============================================================================
// Kernel 3: head weight pack (rows 90..127 zero).
// ============================================================================
__global__ void cvt_wh_kernel(const float* __restrict__ wc, const float* __restrict__ wr) {
    const int j = blockIdx.x;    // 0..127
    const int c = threadIdx.x;   // 0..511
    float v = 0.0f;
    if (j < 30)      v = wc[c * 30 + j];
    else if (j < 90) v = wr[c * 60 + (j - 30)];
    g_wh[(size_t)j * 512 + c] = __float2half(v);
}

// ============================================================================
// Kernel 4: persistent batched GEMM (R10 verbatim: 3-stage, 1 barrier/chunk).
// grid = 1024: mblk(256) x nhalf(2) x chalf(2). 512 thr, 16 warps (2m x 8n),
// warp 64x32, CTA 128x256. 8 comps x 4 chunks per CTA.
// ============================================================================
#define GW_STG     49152u
#define GW_A(s)    ((s) * GW_STG)
#define GW_B(s)    ((s) * GW_STG + 16384u)
#define GW_SMEM    147456
#define GW_NQQ     32

__global__ void __launch_bounds__(512, 1) wino_gemm_kernel()
{
    extern __shared__ char sm[];
    const uint32_t sb = smem_u32(sm);
    const int tid = threadIdx.x;
    const int mblk = blockIdx.x >> 2;
    const int n0 = ((blockIdx.x >> 1) & 1) << 8;
    const int c0 = (blockIdx.x & 1) << 3;
    const int t0 = mblk << 7;

    const int rowA = tid >> 2;
    const int kgA0 = (tid * 2) & 7;
    const int rowB = tid >> 1;
    const int kgB0 = (tid * 4) & 7;
    const uint32_t swA = (uint32_t)(rowA & 7);
    const uint32_t swB = (uint32_t)(rowB & 7);

    const int w = tid >> 5, l = tid & 31;
    const int wm = (w >> 3) * 64, wn = (w & 7) * 32;
    const int lrow = l & 15, hi = l >> 4;
    const uint32_t swL = (uint32_t)(lrow & 7);
    uint32_t aRow[4], bRow[2];
    #pragma unroll
    for (int mt = 0; mt < 4; ++mt) aRow[mt] = (uint32_t)((wm + mt * 16 + lrow) * 128);
    #pragma unroll
    for (int nt = 0; nt < 2; ++nt) bRow[nt] = (uint32_t)((wn + nt * 16 + lrow) * 128);

    float acc[4][4][4];
    #pragma unroll
    for (int mt = 0; mt < 4; ++mt)
        #pragma unroll
        for (int n8 = 0; n8 < 4; ++n8)
            #pragma unroll
            for (int e = 0; e < 4; ++e) acc[mt][n8][e] = 0.0f;

    auto load_chunk = [&](int qq, int s) {
        const int comp = c0 + (qq >> 2), q = qq & 3;
        const uint32_t Ab = sb + GW_A(s), Bb = sb + GW_B(s);
        const char* srcA = reinterpret_cast<const char*>(
            g_V + ((size_t)comp * NTIL + t0 + rowA) * 256 + q * 64);
        #pragma unroll
        for (int i = 0; i < 2; ++i) {
            const int kg = kgA0 + i;
            CP_ASYNC16(Ab + (uint32_t)rowA * 128 + (((uint32_t)kg ^ swA) << 4),
                       srcA + kg * 16, 16);
        }
        const char* srcB = reinterpret_cast<const char*>(
            g_wU + ((size_t)comp * 512 + n0 + rowB) * 256 + q * 64);
        #pragma unroll
        for (int i = 0; i < 4; ++i) {
            const int kg = kgB0 + i;
            CP_ASYNC16(Bb + (uint32_t)rowB * 128 + (((uint32_t)kg ^ swB) << 4),
                       srcB + kg * 16, 16);
        }
    };

    load_chunk(0, 0); CP_COMMIT();
    load_chunk(1, 1); CP_COMMIT();

    const int qrow = l >> 2, qcol = (l & 3) * 2;

    #pragma unroll 1
    for (int qq = 0; qq < GW_NQQ; ++qq) {
        if (qq + 1 < GW_NQQ) CP_WAIT1(); else CP_WAIT0();
        __syncthreads();
        if (qq + 2 < GW_NQQ) { load_chunk(qq + 2, (qq + 2) % 3); CP_COMMIT(); }

        const uint32_t Ab = sb + GW_A(qq % 3), Bb = sb + GW_B(qq % 3);
        #pragma unroll
        for (int ks = 0; ks < 4; ++ks) {
            const uint32_t col = (((uint32_t)(ks * 2 + hi)) ^ swL) << 4;
            uint32_t af[4][4], bf[2][4];
            #pragma unroll
            for (int mt = 0; mt < 4; ++mt) ldm4(af[mt], Ab + aRow[mt] + col);
            #pragma unroll
            for (int nt = 0; nt < 2; ++nt) ldm4(bf[nt], Bb + bRow[nt] + col);
            #pragma unroll
            for (int mt = 0; mt < 4; ++mt)
                #pragma unroll
                for (int n8 = 0; n8 < 4; ++n8)
                    mma16816(acc[mt][n8], af[mt], bf[n8 >> 1][n8 & 1], bf[n8 >> 1][(n8 & 1) + 2]);
        }

        if ((qq & 3) == 3) {
            const int comp = c0 + (qq >> 2);
            __half* Mb = g_M + ((size_t)comp * NTIL + t0) * 512 + n0;
            #pragma unroll
            for (int mt = 0; mt < 4; ++mt) {
                #pragma unroll
                for (int n8 = 0; n8 < 4; ++n8) {
                    const int ch = wn + n8 * 8 + qcol;
                    #pragma unroll
                    for (int hlf = 0; hlf < 2; ++hlf) {
                        const int m = wm + mt * 16 + qrow + hlf * 8;
                        *reinterpret_cast<__half2*>(Mb + (size_t)m * 512 + ch) =
                            __floats2half2_rn(acc[mt][n8][2 * hlf], acc[mt][n8][2 * hlf + 1]);
                        acc[mt][n8][2 * hlf] = 0.0f;
                        acc[mt][n8][2 * hlf + 1] = 0.0f;
                    }
                }
            }
        }
    }
}

// ============================================================================
// Kernel 5: output transform Y = At M A + bias, relu6 -> g_sh (fp16 M input).
// ============================================================================
__global__ void wino_out_kernel(const float* __restrict__ bias) {
    const int t = blockIdx.x;
    const int n2 = threadIdx.x;             // n = 2*n2
    const int tw = t & 63, th = (t >> 6) & 63, b = t >> 12;

    float2 m[4][4];
    #pragma unroll
    for (int i = 0; i < 4; ++i)
        #pragma unroll
        for (int j = 0; j < 4; ++j) {
            __half2 hm = *reinterpret_cast<const __half2*>(
                g_M + ((size_t)(i * 4 + j) * NTIL + t) * 512 + 2 * n2);
            m[i][j] = __half22float2(hm);
        }

    float2 s[2][4];
    #pragma unroll
    for (int j = 0; j < 4; ++j) {
        s[0][j] = make_float2(m[0][j].x + m[1][j].x + m[2][j].x,
                              m[0][j].y + m[1][j].y + m[2][j].y);
        s[1][j] = make_float2(m[1][j].x - m[2][j].x - m[3][j].x,
                              m[1][j].y - m[2][j].y - m[3][j].y);
    }
    const float b0 = bias[2 * n2], b1 = bias[2 * n2 + 1];
    #pragma unroll
    for (int dy = 0; dy < 2; ++dy) {
        float2 y0 = make_float2(s[dy][0].x + s[dy][1].x + s[dy][2].x,
                                s[dy][0].y + s[dy][1].y + s[dy][2].y);
        float2 y1 = make_float2(s[dy][1].x - s[dy][2].x - s[dy][3].x,
                                s[dy][1].y - s[dy][2].y - s[dy][3].y);
        const int h = 2 * th + dy;
        #pragma unroll
        for (int dx = 0; dx < 2; ++dx) {
            const float2 yv = dx ? y1 : y0;
            float v0 = fminf(fmaxf(yv.x + b0, 0.0f), 6.0f);
            float v1 = fminf(fmaxf(yv.y + b1, 0.0f), 6.0f);
            const int w_ = 2 * tw + dx;
            *reinterpret_cast<__half2*>(
                g_sh + ((size_t)((b * 128 + h) * 128 + w_)) * 512 + 2 * n2) =
                __floats2half2_rn(v0, v1);
        }
    }
}

// ============================================================================
// Kernel 6: head GEMM (R8 structure, 256 thr, grid 1024, 2-stage) with warp
// N-tile trimmed 32->24: CTA computes cols 0..95 only (96..127 are zero pad).
// Loaders and smem layout IDENTICAL to the proven R8 kernel.
// ============================================================================
#define HD_A(buf)  ((buf) * 32768u)
#define HD_B(buf)  ((buf) * 32768u + 16384u)
#define HD_BIAS    65536u
#define HD_SMEM    66048
#define HD_NCH     8

__global__ void __launch_bounds__(256, 1) head_kernel(const float* __restrict__ bc,
                                                      const float* __restrict__ br,
                                                      float* __restrict__ out)
{
    extern __shared__ char sm[];
    const uint32_t sb = smem_u32(sm);
    const int tid = threadIdx.x;
    const size_t pos0 = (size_t)blockIdx.x * 128;

    float* hb = reinterpret_cast<float*>(sm + HD_BIAS);
    if (tid < 128)
        hb[tid] = (tid < 30) ? bc[tid] : (tid < 90 ? br[tid - 30] : 0.0f);

    const int rowT = tid >> 1;
    const int kg0 = (tid * 4) & 7;
    const uint32_t swT = (uint32_t)(rowT & 7);

    const int w = tid >> 5, l = tid & 31;
    const int wm = (w >> 2) * 64, wn = (w & 3) * 24;   // N-trim: 24-wide warps
    const int lrow = l & 15, hi = l >> 4;
    const uint32_t swL = (uint32_t)(lrow & 7);
    uint32_t aRow[4], bRow[2];
    #pragma unroll
    for (int mt = 0; mt < 4; ++mt) aRow[mt] = (uint32_t)((wm + mt * 16 + lrow) * 128);
    #pragma unroll
    for (int nt = 0; nt < 2; ++nt) bRow[nt] = (uint32_t)((wn + nt * 16 + lrow) * 128);

    float acc[4][3][4];
    #pragma unroll
    for (int mt = 0; mt < 4; ++mt)
        #pragma unroll
        for (int n8 = 0; n8 < 3; ++n8)
            #pragma unroll
            for (int e = 0; e < 4; ++e) acc[mt][n8][e] = 0.0f;

    auto load_chunk = [&](int q, int buf) {
        const uint32_t Ab = sb + HD_A(buf), Bb = sb + HD_B(buf);
        const char* srcA = reinterpret_cast<const char*>(
            g_sh + (pos0 + rowT) * 512 + q * 64);
        const char* srcB = reinterpret_cast<const char*>(
            g_wh + (size_t)rowT * 512 + q * 64);
        #pragma unroll
        for (int i = 0; i < 4; ++i) {
            const int kg = kg0 + i;
            const uint32_t off = (uint32_t)rowT * 128 + (((uint32_t)kg ^ swT) << 4);
            CP_ASYNC16(Ab + off, srcA + kg * 16, 16);
            CP_ASYNC16(Bb + off, srcB + kg * 16, 16);
        }
    };

    load_chunk(0, 0);
    CP_COMMIT();

    #pragma unroll 1
    for (int q = 0; q < HD_NCH; ++q) {
        if (q + 1 < HD_NCH) {
            load_chunk(q + 1, (q + 1) & 1);
            CP_COMMIT();
            CP_WAIT1();
        } else {
            CP_WAIT0();
        }
        __syncthreads();

        const uint32_t Ab = sb + HD_A(q & 1), Bb = sb + HD_B(q & 1);
        #pragma unroll
        for (int ks = 0; ks < 4; ++ks) {
            const uint32_t col = (((uint32_t)(ks * 2 + hi)) ^ swL) << 4;
            uint32_t af[4][4], bf[2][4];
            #pragma unroll
            for (int mt = 0; mt < 4; ++mt) ldm4(af[mt], Ab + aRow[mt] + col);
            #pragma unroll
            for (int nt = 0; nt < 2; ++nt) ldm4(bf[nt], Bb + bRow[nt] + col);
            #pragma unroll
            for (int mt = 0; mt < 4; ++mt)
                #pragma unroll
                for (int n8 = 0; n8 < 3; ++n8)
                    mma16816(acc[mt][n8], af[mt], bf[n8 >> 1][n8 & 1], bf[n8 >> 1][(n8 & 1) + 2]);
        }
        __syncthreads();
    }

    const int qrow = l >> 2, qcol = (l & 3) * 2;
    #pragma unroll
    for (int mt = 0; mt < 4; ++mt) {
        #pragma unroll
        for (int n8 = 0; n8 < 3; ++n8) {
            const int ch = wn + n8 * 8 + qcol;        // 0..94, even
            if (ch >= 90) continue;
            const float b0 = hb[ch], b1 = hb[ch + 1];
            #pragma unroll
            for (int hlf = 0; hlf < 2; ++hlf) {
                const int m = wm + mt * 16 + qrow + hlf * 8;
                const size_t pos = pos0 + m;
                const float v0 = acc[mt][n8][2 * hlf]     + b0;
                const float v1 = acc[mt][n8][2 * hlf + 1] + b1;
                if (ch < 30) {
                    *reinterpret_cast<float2*>(out + pos * 30 + ch) = make_float2(v0, v1);
                    const float mx = fmaxf(v0, v1);
                    const float e0 = __expf(v0 - mx), e1 = __expf(v1 - mx);
                    const float inv = 1.0f / (e0 + e1);
                    *reinterpret_cast<float2*>(out + OFF_PROBS + pos * 30 + ch) =
                        make_float2(e0 * inv, e1 * inv);
                } else {
                    *reinterpret_cast<float2*>(out + OFF_DELTAS + pos * 60 + (ch - 30)) =
                        make_float2(v0, v1);
                }
            }
        }
    }
}

// ============================================================================
// Launch
// ============================================================================
extern "C" void kernel_launch(void* const* d_in, const int* in_sizes, int n_in,
                              void* d_out, int out_size) {
    const float* x  = (const float*)d_in[0];
    const float* ws = (const float*)d_in[1];
    const float* bs = (const float*)d_in[2];
    const float* wc = (const float*)d_in[3];
    const float* bc = (const float*)d_in[4];
    const float* wr = (const float*)d_in[5];
    const float* br = (const float*)d_in[6];
    float* out = (float*)d_out;

    cudaFuncSetAttribute(wino_gemm_kernel, cudaFuncAttributeMaxDynamicSharedMemorySize, GW_SMEM);
    cudaFuncSetAttribute(head_kernel, cudaFuncAttributeMaxDynamicSharedMemorySize, HD_SMEM);

    wino_in_kernel<<<NTIL, 128>>>(x);
    wino_w_kernel<<<512, 256>>>(ws);
    cvt_wh_kernel<<<128, 512>>>(wc, wr);
    wino_gemm_kernel<<<1024, 512, GW_SMEM>>>();
    wino_out_kernel<<<NTIL, 256>>>(bs);
    head_kernel<<<1024, 256, HD_SMEM>>>(bc, br, out);
}

// round 13
// speedup vs baseline: 1.5669x; 1.0008x over previous
#include <cuda_runtime.h>
#include <cuda_fp16.h>
#include <cstdint>

// ============================================================================
// RPNHead via Winograd F(2x2,3x3). R13:
//  - GEMM: 4-stage cp.async pipeline (prefetch distance 3), one barrier/chunk.
//  - wino_in: 8 tiles per block with a sliding 2-column register window
//    (44% fewer x reads). Outputs bit-identical.
//  - head: R12's trimmed 24-wide warp N-tile (proven).
// ============================================================================
#define NPOS 131072
#define NTIL 32768
#define OFF_PROBS  3932160
#define OFF_DELTAS 7864320

__device__ __align__(1024) __half g_V [(size_t)16*NTIL*256];   // input transform
__device__ __align__(1024) __half g_wU[(size_t)16*512*256];    // weight transform
__device__ __align__(1024) __half g_M [(size_t)16*NTIL*512];   // GEMM results (fp16)
__device__ __align__(1024) __half g_sh[(size_t)NPOS*512];      // shared acts fp16
__device__ __align__(1024) __half g_wh[(size_t)128*512];       // head W [j][c]

__device__ __forceinline__ uint32_t smem_u32(const void* p) {
    uint32_t a;
    asm("{ .reg .u64 t; cvta.to.shared.u64 t, %1; cvt.u32.u64 %0, t; }"
        : "=r"(a) : "l"(p));
    return a;
}

#define CP_ASYNC16(dst, src, sz) \
    asm volatile("cp.async.cg.shared.global [%0], [%1], 16, %2;" \
        :: "r"((uint32_t)(dst)), "l"(src), "r"((int)(sz)) : "memory")
#define CP_COMMIT() asm volatile("cp.async.commit_group;" ::: "memory")
#define CP_WAIT2()  asm volatile("cp.async.wait_group 2;" ::: "memory")
#define CP_WAIT1()  asm volatile("cp.async.wait_group 1;" ::: "memory")
#define CP_WAIT0()  asm volatile("cp.async.wait_group 0;" ::: "memory")

__device__ __forceinline__ void ldm4(uint32_t* f, uint32_t addr) {
    asm volatile("ldmatrix.sync.aligned.m8n8.x4.shared.b16 {%0,%1,%2,%3}, [%4];"
        : "=r"(f[0]), "=r"(f[1]), "=r"(f[2]), "=r"(f[3]) : "r"(addr));
}
__device__ __forceinline__ void mma16816(float* c, const uint32_t* a,
                                         uint32_t b0, uint32_t b1) {
    asm volatile("mma.sync.aligned.m16n8k16.row.col.f32.f16.f16.f32 "
        "{%0,%1,%2,%3}, {%4,%5,%6,%7}, {%8,%9}, {%0,%1,%2,%3};"
        : "+f"(c[0]), "+f"(c[1]), "+f"(c[2]), "+f"(c[3])
        : "r"(a[0]), "r"(a[1]), "r"(a[2]), "r"(a[3]), "r"(b0), "r"(b1));
}

// ============================================================================
// Kernel 1: input transform V = Bt d B, 8 tiles per block, sliding window.
// grid = 4096: b(8) x th(64) x wgrp(8). 128 threads (channel pairs).
// ============================================================================
__global__ void wino_in_kernel(const float* __restrict__ x) {
    const int blk = blockIdx.x;
    const int wgrp = blk & 7;
    const int th = (blk >> 3) & 63;
    const int b = blk >> 9;
    const int c2 = threadIdx.x;
    const int tw0 = wgrp * 8;
    const int h0 = th * 2 - 1;
    const int wbase = tw0 * 2 - 1;          // global w of window col 0

    bool hv[4];
    const float* rowp[4];
    #pragma unroll
    for (int i = 0; i < 4; ++i) {
        const int h = h0 + i;
        hv[i] = (h >= 0) && (h < 128);
        rowp[i] = x + ((size_t)((b * 128 + (hv[i] ? h : 0)) * 128)) * 256 + 2 * c2;
    }

    auto ldcol = [&](int i, int wc) -> float2 {
        if (hv[i] && wc >= 0 && wc < 128)
            return *reinterpret_cast<const float2*>(rowp[i] + (size_t)wc * 256);
        return make_float2(0.0f, 0.0f);
    };

    float2 d[4][4];
    #pragma unroll
    for (int i = 0; i < 4; ++i)
        #pragma unroll
        for (int j = 0; j < 4; ++j)
            d[i][j] = ldcol(i, wbase + j);

    #pragma unroll
    for (int k = 0; k < 8; ++k) {
        // transform current window -> tile t
        const int t = (b * 64 + th) * 64 + (tw0 + k);
        float2 tr[4][4];
        #pragma unroll
        for (int j = 0; j < 4; ++j) {
            tr[0][j] = make_float2(d[0][j].x - d[2][j].x, d[0][j].y - d[2][j].y);
            tr[1][j] = make_float2(d[1][j].x + d[2][j].x, d[1][j].y + d[2][j].y);
            tr[2][j] = make_float2(d[2][j].x - d[1][j].x, d[2][j].y - d[1][j].y);
            tr[3][j] = make_float2(d[1][j].x - d[3][j].x, d[1][j].y - d[3][j].y);
        }
        #pragma unroll
        for (int i = 0; i < 4; ++i) {
            float2 v0 = make_float2(tr[i][0].x - tr[i][2].x, tr[i][0].y - tr[i][2].y);
            float2 v1 = make_float2(tr[i][1].x + tr[i][2].x, tr[i][1].y + tr[i][2].y);
            float2 v2 = make_float2(tr[i][2].x - tr[i][1].x, tr[i][2].y - tr[i][1].y);
            float2 v3 = make_float2(tr[i][1].x - tr[i][3].x, tr[i][1].y - tr[i][3].y);
            *reinterpret_cast<__half2*>(g_V + ((size_t)(i*4+0)*NTIL + t)*256 + 2*c2) = __floats2half2_rn(v0.x, v0.y);
            *reinterpret_cast<__half2*>(g_V + ((size_t)(i*4+1)*NTIL + t)*256 + 2*c2) = __floats2half2_rn(v1.x, v1.y);
            *reinterpret_cast<__half2*>(g_V + ((size_t)(i*4+2)*NTIL + t)*256 + 2*c2) = __floats2half2_rn(v2.x, v2.y);
            *reinterpret_cast<__half2*>(g_V + ((size_t)(i*4+3)*NTIL + t)*256 + 2*c2) = __floats2half2_rn(v3.x, v3.y);
        }
        if (k < 7) {
            // slide window by 2 columns
            #pragma unroll
            for (int i = 0; i < 4; ++i) {
                d[i][0] = d[i][2];
                d[i][1] = d[i][3];
                d[i][2] = ldcol(i, wbase + 2 * k + 4);
                d[i][3] = ldcol(i, wbase + 2 * k + 5);
            }
        }
    }
}

// ============================================================================
// Kernel 2: weight transform U = G g Gt. grid=512 (n), block=256 (c).
// ============================================================================
__global__ void wino_w_kernel(const float* __restrict__ ws) {
    const int n = blockIdx.x;
    const int c = threadIdx.x;
    float g[3][3];
    #pragma unroll
    for (int kh = 0; kh < 3; ++kh)
        #pragma unroll
        for (int kw = 0; kw < 3; ++kw)
            g[kh][kw] = ws[((size_t)(kh * 3 + kw) * 256 + c) * 512 + n];
    float u[4][3];
    #pragma unroll
    for (int kw = 0; kw < 3; ++kw) {
        u[0][kw] = g[0][kw];
        u[1][kw] = 0.5f * (g[0][kw] + g[1][kw] + g[2][kw]);
        u[2][kw] = 0.5f * (g[0][kw] - g[1][kw] + g[2][kw]);
        u[3][kw] = g[2][kw];
    }
    #pragma unroll
    for (int r = 0; r < 4; ++r) {
        float U0 = u[r][0];
        float U1 = 0.5f * (u[r][0] + u[r][1] + u[r][2]);
        float U2 = 0.5f * (u[r][0] - u[r][1] + u[r][2]);
        float U3 = u[r][2];
        g_wU[((size_t)(r * 4 + 0) * 512 + n) * 256 + c] = __float2half(U0);
        g_wU[((size_t)(r * 4 + 1) * 512 + n) * 256 + c] = __float2half(U1);
        g_wU[((size_t)(r * 4 + 2) * 512 + n) * 256 + c] = __float2half(U2);
        g_wU[((size_t)(r * 4 + 3) * 512 + n) * 256 + c] = __float2half(U3);
    }
}

// ============================================================================
// Kernel 3: head weight pack (rows 90..127 zero).
// ============================================================================
__global__ void cvt_wh_kernel(const float* __restrict__ wc, const float* __restrict__ wr) {
    const int j = blockIdx.x;    // 0..127
    const int c = threadIdx.x;   // 0..511
    float v = 0.0f;
    if (j < 30)      v = wc[c * 30 + j];
    else if (j < 90) v = wr[c * 60 + (j - 30)];
    g_wh[(size_t)j * 512 + c] = __float2half(v);
}

// ============================================================================
// Kernel 4: persistent batched GEMM — 4-stage pipeline, distance-3 prefetch,
// one barrier per chunk. 512 thr, 16 warps (2m x 8n), warp 64x32, CTA 128x256.
// grid = 1024: mblk(256) x nhalf(2) x chalf(2); 8 comps x 4 chunks per CTA.
// SMEM: 4 x 48KB = 192KB.
// ============================================================================
#define GW_STG     49152u
#define GW_A(s)    ((s) * GW_STG)
#define GW_B(s)    ((s) * GW_STG + 16384u)
#define GW_SMEM    196608
#define GW_NQQ     32

__global__ void __launch_bounds__(512, 1) wino_gemm_kernel()
{
    extern __shared__ char sm[];
    const uint32_t sb = smem_u32(sm);
    const int tid = threadIdx.x;
    const int mblk = blockIdx.x >> 2;
    const int n0 = ((blockIdx.x >> 1) & 1) << 8;
    const int c0 = (blockIdx.x & 1) << 3;
    const int t0 = mblk << 7;

    const int rowA = tid >> 2;
    const int kgA0 = (tid * 2) & 7;
    const int rowB = tid >> 1;
    const int kgB0 = (tid * 4) & 7;
    const uint32_t swA = (uint32_t)(rowA & 7);
    const uint32_t swB = (uint32_t)(rowB & 7);

    const int w = tid >> 5, l = tid & 31;
    const int wm = (w >> 3) * 64, wn = (w & 7) * 32;
    const int lrow = l & 15, hi = l >> 4;
    const uint32_t swL = (uint32_t)(lrow & 7);
    uint32_t aRow[4], bRow[2];
    #pragma unroll
    for (int mt = 0; mt < 4; ++mt) aRow[mt] = (uint32_t)((wm + mt * 16 + lrow) * 128);
    #pragma unroll
    for (int nt = 0; nt < 2; ++nt) bRow[nt] = (uint32_t)((wn + nt * 16 + lrow) * 128);

    float acc[4][4][4];
    #pragma unroll
    for (int mt = 0; mt < 4; ++mt)
        #pragma unroll
        for (int n8 = 0; n8 < 4; ++n8)
            #pragma unroll
            for (int e = 0; e < 4; ++e) acc[mt][n8][e] = 0.0f;

    auto load_chunk = [&](int qq, int s) {
        const int comp = c0 + (qq >> 2), q = qq & 3;
        const uint32_t Ab = sb + GW_A(s), Bb = sb + GW_B(s);
        const char* srcA = reinterpret_cast<const char*>(
            g_V + ((size_t)comp * NTIL + t0 + rowA) * 256 + q * 64);
        #pragma unroll
        for (int i = 0; i < 2; ++i) {
            const int kg = kgA0 + i;
            CP_ASYNC16(Ab + (uint32_t)rowA * 128 + (((uint32_t)kg ^ swA) << 4),
                       srcA + kg * 16, 16);
        }
        const char* srcB = reinterpret_cast<const char*>(
            g_wU + ((size_t)comp * 512 + n0 + rowB) * 256 + q * 64);
        #pragma unroll
        for (int i = 0; i < 4; ++i) {
            const int kg = kgB0 + i;
            CP_ASYNC16(Bb + (uint32_t)rowB * 128 + (((uint32_t)kg ^ swB) << 4),
                       srcB + kg * 16, 16);
        }
    };

    load_chunk(0, 0); CP_COMMIT();
    load_chunk(1, 1); CP_COMMIT();
    load_chunk(2, 2); CP_COMMIT();

    const int qrow = l >> 2, qcol = (l & 3) * 2;

    #pragma unroll 1
    for (int qq = 0; qq < GW_NQQ; ++qq) {
        CP_WAIT2();          // group qq complete (empty tail commits keep numbering)
        __syncthreads();
        if (qq + 3 < GW_NQQ) load_chunk(qq + 3, (qq + 3) & 3);
        CP_COMMIT();

        const uint32_t Ab = sb + GW_A(qq & 3), Bb = sb + GW_B(qq & 3);
        #pragma unroll
        for (int ks = 0; ks < 4; ++ks) {
            const uint32_t col = (((uint32_t)(ks * 2 + hi)) ^ swL) << 4;
            uint32_t af[4][4], bf[2][4];
            #pragma unroll
            for (int mt = 0; mt < 4; ++mt) ldm4(af[mt], Ab + aRow[mt] + col);
            #pragma unroll
            for (int nt = 0; nt < 2; ++nt) ldm4(bf[nt], Bb + bRow[nt] + col);
            #pragma unroll
            for (int mt = 0; mt < 4; ++mt)
                #pragma unroll
                for (int n8 = 0; n8 < 4; ++n8)
                    mma16816(acc[mt][n8], af[mt], bf[n8 >> 1][n8 & 1], bf[n8 >> 1][(n8 & 1) + 2]);
        }

        if ((qq & 3) == 3) {
            const int comp = c0 + (qq >> 2);
            __half* Mb = g_M + ((size_t)comp * NTIL + t0) * 512 + n0;
            #pragma unroll
            for (int mt = 0; mt < 4; ++mt) {
                #pragma unroll
                for (int n8 = 0; n8 < 4; ++n8) {
                    const int ch = wn + n8 * 8 + qcol;
                    #pragma unroll
                    for (int hlf = 0; hlf < 2; ++hlf) {
                        const int m = wm + mt * 16 + qrow + hlf * 8;
                        *reinterpret_cast<__half2*>(Mb + (size_t)m * 512 + ch) =
                            __floats2half2_rn(acc[mt][n8][2 * hlf], acc[mt][n8][2 * hlf + 1]);
                        acc[mt][n8][2 * hlf] = 0.0f;
                        acc[mt][n8][2 * hlf + 1] = 0.0f;
                    }
                }
            }
        }
    }
}

// ============================================================================
// Kernel 5: output transform Y = At M A + bias, relu6 -> g_sh (fp16 M input).
// ============================================================================
__global__ void wino_out_kernel(const float* __restrict__ bias) {
    const int t = blockIdx.x;
    const int n2 = threadIdx.x;             // n = 2*n2
    const int tw = t & 63, th = (t >> 6) & 63, b = t >> 12;

    float2 m[4][4];
    #pragma unroll
    for (int i = 0; i < 4; ++i)
        #pragma unroll
        for (int j = 0; j < 4; ++j) {
            __half2 hm = *reinterpret_cast<const __half2*>(
                g_M + ((size_t)(i * 4 + j) * NTIL + t) * 512 + 2 * n2);
            m[i][j] = __half22float2(hm);
        }

    float2 s[2][4];
    #pragma unroll
    for (int j = 0; j < 4; ++j) {
        s[0][j] = make_float2(m[0][j].x + m[1][j].x + m[2][j].x,
                              m[0][j].y + m[1][j].y + m[2][j].y);
        s[1][j] = make_float2(m[1][j].x - m[2][j].x - m[3][j].x,
                              m[1][j].y - m[2][j].y - m[3][j].y);
    }
    const float b0 = bias[2 * n2], b1 = bias[2 * n2 + 1];
    #pragma unroll
    for (int dy = 0; dy < 2; ++dy) {
        float2 y0 = make_float2(s[dy][0].x + s[dy][1].x + s[dy][2].x,
                                s[dy][0].y + s[dy][1].y + s[dy][2].y);
        float2 y1 = make_float2(s[dy][1].x - s[dy][2].x - s[dy][3].x,
                                s[dy][1].y - s[dy][2].y - s[dy][3].y);
        const int h = 2 * th + dy;
        #pragma unroll
        for (int dx = 0; dx < 2; ++dx) {
            const float2 yv = dx ? y1 : y0;
            float v0 = fminf(fmaxf(yv.x + b0, 0.0f), 6.0f);
            float v1 = fminf(fmaxf(yv.y + b1, 0.0f), 6.0f);
            const int w_ = 2 * tw + dx;
            *reinterpret_cast<__half2*>(
                g_sh + ((size_t)((b * 128 + h) * 128 + w_)) * 512 + 2 * n2) =
                __floats2half2_rn(v0, v1);
        }
    }
}

// ============================================================================
// Kernel 6: head GEMM (256 thr, grid 1024, 2-stage, warp N-tile 24).
// ============================================================================
#define HD_A(buf)  ((buf) * 32768u)
#define HD_B(buf)  ((buf) * 32768u + 16384u)
#define HD_BIAS    65536u
#define HD_SMEM    66048
#define HD_NCH     8

__global__ void __launch_bounds__(256, 1) head_kernel(const float* __restrict__ bc,
                                                      const float* __restrict__ br,
                                                      float* __restrict__ out)
{
    extern __shared__ char sm[];
    const uint32_t sb = smem_u32(sm);
    const int tid = threadIdx.x;
    const size_t pos0 = (size_t)blockIdx.x * 128;

    float* hb = reinterpret_cast<float*>(sm + HD_BIAS);
    if (tid < 128)
        hb[tid] = (tid < 30) ? bc[tid] : (tid < 90 ? br[tid - 30] : 0.0f);

    const int rowT = tid >> 1;
    const int kg0 = (tid * 4) & 7;
    const uint32_t swT = (uint32_t)(rowT & 7);

    const int w = tid >> 5, l = tid & 31;
    const int wm = (w >> 2) * 64, wn = (w & 3) * 24;
    const int lrow = l & 15, hi = l >> 4;
    const uint32_t swL = (uint32_t)(lrow & 7);
    uint32_t aRow[4], bRow[2];
    #pragma unroll
    for (int mt = 0; mt < 4; ++mt) aRow[mt] = (uint32_t)((wm + mt * 16 + lrow) * 128);
    #pragma unroll
    for (int nt = 0; nt < 2; ++nt) bRow[nt] = (uint32_t)((wn + nt * 16 + lrow) * 128);

    float acc[4][3][4];
    #pragma unroll
    for (int mt = 0; mt < 4; ++mt)
        #pragma unroll
        for (int n8 = 0; n8 < 3; ++n8)
            #pragma unroll
            for (int e = 0; e < 4; ++e) acc[mt][n8][e] = 0.0f;

    auto load_chunk = [&](int q, int buf) {
        const uint32_t Ab = sb + HD_A(buf), Bb = sb + HD_B(buf);
        const char* srcA = reinterpret_cast<const char*>(
            g_sh + (pos0 + rowT) * 512 + q * 64);
        const char* srcB = reinterpret_cast<const char*>(
            g_wh + (size_t)rowT * 512 + q * 64);
        #pragma unroll
        for (int i = 0; i < 4; ++i) {
            const int kg = kg0 + i;
            const uint32_t off = (uint32_t)rowT * 128 + (((uint32_t)kg ^ swT) << 4);
            CP_ASYNC16(Ab + off, srcA + kg * 16, 16);
            CP_ASYNC16(Bb + off, srcB + kg * 16, 16);
        }
    };

    load_chunk(0, 0);
    CP_COMMIT();

    #pragma unroll 1
    for (int q = 0; q < HD_NCH; ++q) {
        if (q + 1 < HD_NCH) {
            load_chunk(q + 1, (q + 1) & 1);
            CP_COMMIT();
            CP_WAIT1();
        } else {
            CP_WAIT0();
        }
        __syncthreads();

        const uint32_t Ab = sb + HD_A(q & 1), Bb = sb + HD_B(q & 1);
        #pragma unroll
        for (int ks = 0; ks < 4; ++ks) {
            const uint32_t col = (((uint32_t)(ks * 2 + hi)) ^ swL) << 4;
            uint32_t af[4][4], bf[2][4];
            #pragma unroll
            for (int mt = 0; mt < 4; ++mt) ldm4(af[mt], Ab + aRow[mt] + col);
            #pragma unroll
            for (int nt = 0; nt < 2; ++nt) ldm4(bf[nt], Bb + bRow[nt] + col);
            #pragma unroll
            for (int mt = 0; mt < 4; ++mt)
                #pragma unroll
                for (int n8 = 0; n8 < 3; ++n8)
                    mma16816(acc[mt][n8], af[mt], bf[n8 >> 1][n8 & 1], bf[n8 >> 1][(n8 & 1) + 2]);
        }
        __syncthreads();
    }

    const int qrow = l >> 2, qcol = (l & 3) * 2;
    #pragma unroll
    for (int mt = 0; mt < 4; ++mt) {
        #pragma unroll
        for (int n8 = 0; n8 < 3; ++n8) {
            const int ch = wn + n8 * 8 + qcol;
            if (ch >= 90) continue;
            const float b0 = hb[ch], b1 = hb[ch + 1];
            #pragma unroll
            for (int hlf = 0; hlf < 2; ++hlf) {
                const int m = wm + mt * 16 + qrow + hlf * 8;
                const size_t pos = pos0 + m;
                const float v0 = acc[mt][n8][2 * hlf]     + b0;
                const float v1 = acc[mt][n8][2 * hlf + 1] + b1;
                if (ch < 30) {
                    *reinterpret_cast<float2*>(out + pos * 30 + ch) = make_float2(v0, v1);
                    const float mx = fmaxf(v0, v1);
                    const float e0 = __expf(v0 - mx), e1 = __expf(v1 - mx);
                    const float inv = 1.0f / (e0 + e1);
                    *reinterpret_cast<float2*>(out + OFF_PROBS + pos * 30 + ch) =
                        make_float2(e0 * inv, e1 * inv);
                } else {
                    *reinterpret_cast<float2*>(out + OFF_DELTAS + pos * 60 + (ch - 30)) =
                        make_float2(v0, v1);
                }
            }
        }
    }
}

// ============================================================================
// Launch
// ============================================================================
extern "C" void kernel_launch(void* const* d_in, const int* in_sizes, int n_in,
                              void* d_out, int out_size) {
    const float* x  = (const float*)d_in[0];
    const float* ws = (const float*)d_in[1];
    const float* bs = (const float*)d_in[2];
    const float* wc = (const float*)d_in[3];
    const float* bc = (const float*)d_in[4];
    const float* wr = (const float*)d_in[5];
    const float* br = (const float*)d_in[6];
    float* out = (float*)d_out;

    cudaFuncSetAttribute(wino_gemm_kernel, cudaFuncAttributeMaxDynamicSharedMemorySize, GW_SMEM);
    cudaFuncSetAttribute(head_kernel, cudaFuncAttributeMaxDynamicSharedMemorySize, HD_SMEM);

    wino_in_kernel<<<4096, 128>>>(x);
    wino_w_kernel<<<512, 256>>>(ws);
    cvt_wh_kernel<<<128, 512>>>(wc, wr);
    wino_gemm_kernel<<<1024, 512, GW_SMEM>>>();
    wino_out_kernel<<<NTIL, 256>>>(bs);
    head_kernel<<<1024, 256, HD_SMEM>>>(bc, br, out);
}